// round 9
// baseline (speedup 1.0000x reference)
#include <cuda_runtime.h>

// PGJANET recurrent scan: B=256, T=2048, H=64, O=2.
// 128 blocks x 288 threads (8 compute warps + 1 y-warp), 2 elems per block.
// Thread (j = tid>>2, s = tid&3): unit j, slice s; the 4 slice lanes of a
// unit are ADJACENT, so slice reduction = 2x shfl_xor (no smem partials, no
// extra barriers). Finalize is fused into the same segment: lane s computes
// gate s (branchless), u = cross-lane shfl product. 2 __syncthreads/step.
// Scalar FFMA (f32x2 disproven R2/R5/R7). Ping-pong hbuf kills WAR hazard.

#define TB 2048

__device__ __forceinline__ float sigf(float v) {
    return __fdividef(1.f, 1.f + __expf(-v));
}
__device__ __forceinline__ float tanhfast(float v) {
    return fmaf(2.f, sigf(2.f * v), -1.f);
}

__global__ void __launch_bounds__(288, 1)
pgjanet_kernel(const float* __restrict__ x,
               const float* __restrict__ h0,
               const float* __restrict__ Wa,  const float* __restrict__ ba,
               const float* __restrict__ Wp1, const float* __restrict__ bp1,
               const float* __restrict__ Wp2, const float* __restrict__ bp2,
               const float* __restrict__ Wf,  const float* __restrict__ bf,
               const float* __restrict__ Wg,  const float* __restrict__ bg,
               const float* __restrict__ Wo,  const float* __restrict__ bo,
               float* __restrict__ out)
{
    __shared__ __align__(16) float2 xb[2][TB];      // 32 KB
    __shared__ __align__(16) float hbuf[2][2][64];  // ping-pong [buf][elem][unit]
    __shared__ __align__(16) float ubuf[2][64];     // [elem][unit]

    const int tid  = threadIdx.x;
    const int lane = tid & 31;
    const int wid  = tid >> 5;
    const bool comp = (tid < 256);
    const int j    = (tid & 255) >> 2;   // unit 0..63 (compute threads)
    const int s    = tid & 3;            // slice 0..3
    const int b0   = blockIdx.x * 2;

    // ---- weights in registers (112 floats, compute threads) ----
    float wa[16], wp1[16], wp2[16], wfh[16], wgh[16], wfu[16], wgu[16];
    if (comp) {
        const float* A = Wa  + j * 65 + s * 16;
        const float* P = Wp1 + j * 65 + s * 16;
        const float* Q = Wp2 + j * 65 + s * 16;
        const float* F = Wf  + j * 128 + s * 16;
        const float* G = Wg  + j * 128 + s * 16;
        #pragma unroll
        for (int i = 0; i < 16; i++) {
            wa[i]  = A[i];  wp1[i] = P[i];  wp2[i] = Q[i];
            wfh[i] = F[i];  wgh[i] = G[i];
            wfu[i] = F[64 + i]; wgu[i] = G[64 + i];
        }
    }

    // ---- per-lane gate constants ----
    // segA: lane s handles gate (0:a, 1:p1, 2:p2, 3:dup-a with v forced to 1)
    float wlast = 0.f, pb = 0.f;
    if (comp) {
        const float* Wl = (s == 1) ? Wp1 : (s == 2) ? Wp2 : Wa;
        const float* bl = (s == 1) ? bp1 : (s == 2) ? bp2 : ba;
        wlast = Wl[j * 65 + 64];
        pb    = bl[j];
    }
    // segB: lane s handles (elem = s&1, func = s>>1 : 0=f(sigmoid), 1=g(tanh))
    const int   e_mine = s & 1;
    const bool  is_g   = (s >> 1) != 0;
    float bias2 = 0.f;
    if (comp) bias2 = is_g ? bg[j] : bf[j];

    // ---- y-warp constants (warp 8) ----
    float wo0a = 0.f, wo0b = 0.f, wo1a = 0.f, wo1b = 0.f, bo0 = 0.f, bo1 = 0.f;
    if (wid == 8) {
        wo0a = Wo[lane];      wo0b = Wo[lane + 32];
        wo1a = Wo[64 + lane]; wo1b = Wo[96 + lane];
        bo0 = bo[0]; bo1 = bo[1];
    }

    // ---- preload x + h0 ----
    {
        const float2* xg0 = (const float2*)x + (size_t)b0 * TB;
        const float2* xg1 = (const float2*)x + (size_t)(b0 + 1) * TB;
        for (int i = tid; i < TB; i += 288) { xb[0][i] = xg0[i]; xb[1][i] = xg1[i]; }
    }
    if (tid < 128) hbuf[0][tid >> 6][tid & 63] = h0[(size_t)(b0 + (tid >> 6)) * 64 + (tid & 63)];
    __syncthreads();

    #pragma unroll 1
    for (int t = 0; t < TB; t++) {
        const int cur = t & 1, nxt = cur ^ 1;

        if (comp) {
            // ==== segment A: a/p1/p2 dots + shfl reduce + fused u-finalize ====
            const float4* hA = (const float4*)&hbuf[cur][0][s * 16];
            const float4* hB = (const float4*)&hbuf[cur][1][s * 16];
            float a0 = 0.f, p0 = 0.f, q0 = 0.f;
            float a1 = 0.f, p1 = 0.f, q1 = 0.f;
            #pragma unroll
            for (int r = 0; r < 4; r++) {
                float4 v0 = hA[r], v1 = hB[r];
                a0 = fmaf(wa [4*r+0], v0.x, a0); a1 = fmaf(wa [4*r+0], v1.x, a1);
                p0 = fmaf(wp1[4*r+0], v0.x, p0); p1 = fmaf(wp1[4*r+0], v1.x, p1);
                q0 = fmaf(wp2[4*r+0], v0.x, q0); q1 = fmaf(wp2[4*r+0], v1.x, q1);
                a0 = fmaf(wa [4*r+1], v0.y, a0); a1 = fmaf(wa [4*r+1], v1.y, a1);
                p0 = fmaf(wp1[4*r+1], v0.y, p0); p1 = fmaf(wp1[4*r+1], v1.y, p1);
                q0 = fmaf(wp2[4*r+1], v0.y, q0); q1 = fmaf(wp2[4*r+1], v1.y, q1);
                a0 = fmaf(wa [4*r+2], v0.z, a0); a1 = fmaf(wa [4*r+2], v1.z, a1);
                p0 = fmaf(wp1[4*r+2], v0.z, p0); p1 = fmaf(wp1[4*r+2], v1.z, p1);
                q0 = fmaf(wp2[4*r+2], v0.z, q0); q1 = fmaf(wp2[4*r+2], v1.z, q1);
                a0 = fmaf(wa [4*r+3], v0.w, a0); a1 = fmaf(wa [4*r+3], v1.w, a1);
                p0 = fmaf(wp1[4*r+3], v0.w, p0); p1 = fmaf(wp1[4*r+3], v1.w, p1);
                q0 = fmaf(wp2[4*r+3], v0.w, q0); q1 = fmaf(wp2[4*r+3], v1.w, q1);
            }
            // 2-stage intra-group reduction (lanes 4m..4m+3 share unit j)
            a0 += __shfl_xor_sync(~0u, a0, 1); p0 += __shfl_xor_sync(~0u, p0, 1);
            q0 += __shfl_xor_sync(~0u, q0, 1); a1 += __shfl_xor_sync(~0u, a1, 1);
            p1 += __shfl_xor_sync(~0u, p1, 1); q1 += __shfl_xor_sync(~0u, q1, 1);
            a0 += __shfl_xor_sync(~0u, a0, 2); p0 += __shfl_xor_sync(~0u, p0, 2);
            q0 += __shfl_xor_sync(~0u, q0, 2); a1 += __shfl_xor_sync(~0u, a1, 2);
            p1 += __shfl_xor_sync(~0u, p1, 2); q1 += __shfl_xor_sync(~0u, q1, 2);

            // per-lane scalar input (gate s): 0->amp, 1->cos, 2->sin
            float2 x0 = xb[0][t], x1 = xb[1][t];
            float s20 = fmaf(x0.x, x0.x, x0.y * x0.y);
            float s21 = fmaf(x1.x, x1.x, x1.y * x1.y);
            float ri0 = rsqrtf(s20), ri1 = rsqrtf(s21);
            float c0 = (s == 1) ? x0.x : (s == 2) ? x0.y : s20;
            float c1 = (s == 1) ? x1.x : (s == 2) ? x1.y : s21;
            float dflt = (s == 1) ? 1.f : 0.f;
            float in0 = (s20 > 0.f) ? c0 * ri0 : dflt;
            float in1 = (s21 > 0.f) ? c1 * ri1 : dflt;

            // gate value for this lane (branchless select)
            float sum0 = (s == 1) ? p0 : (s == 2) ? q0 : a0;
            float sum1 = (s == 1) ? p1 : (s == 2) ? q1 : a1;
            float tv0 = tanhfast(fmaf(in0, wlast, sum0 + pb));
            float tv1 = tanhfast(fmaf(in1, wlast, sum1 + pb));
            float v0 = fmaf(-tv0, tv0, tv0);   // t*(1-t)
            float v1 = fmaf(-tv1, tv1, tv1);
            if (s == 3) { v0 = 1.f; v1 = 1.f; }
            // cross-lane product -> u
            v0 *= __shfl_xor_sync(~0u, v0, 1);
            v1 *= __shfl_xor_sync(~0u, v1, 1);
            v0 *= __shfl_xor_sync(~0u, v0, 2);
            v1 *= __shfl_xor_sync(~0u, v1, 2);
            if (s == 0) ubuf[0][j] = v0;
            if (s == 1) ubuf[1][j] = v1;
        } else if (t > 0) {
            // ==== y-warp: y_{t-1} = Wo . h_{t-1} for both elems ====
            float ha0 = hbuf[cur][0][lane], hb0 = hbuf[cur][0][lane + 32];
            float ha1 = hbuf[cur][1][lane], hb1 = hbuf[cur][1][lane + 32];
            float y00 = ha0 * wo0a + hb0 * wo0b;
            float y01 = ha0 * wo1a + hb0 * wo1b;
            float y10 = ha1 * wo0a + hb1 * wo0b;
            float y11 = ha1 * wo1a + hb1 * wo1b;
            #pragma unroll
            for (int off = 16; off; off >>= 1) {
                y00 += __shfl_xor_sync(~0u, y00, off);
                y01 += __shfl_xor_sync(~0u, y01, off);
                y10 += __shfl_xor_sync(~0u, y10, off);
                y11 += __shfl_xor_sync(~0u, y11, off);
            }
            if (lane == 0) {
                ((float2*)out)[(size_t)b0 * TB + (t - 1)] =
                    make_float2(y00 + bo0, y01 + bo1);
                ((float2*)out)[(size_t)(b0 + 1) * TB + (t - 1)] =
                    make_float2(y10 + bo0, y11 + bo1);
            }
        }
        __syncthreads();   // #1: ubuf published

        if (comp) {
            // ==== segment B: f/g dots over [h | u] + fused h-finalize ====
            const float4* hA = (const float4*)&hbuf[cur][0][s * 16];
            const float4* hB = (const float4*)&hbuf[cur][1][s * 16];
            const float4* uA = (const float4*)&ubuf[0][s * 16];
            const float4* uB = (const float4*)&ubuf[1][s * 16];
            float hold = hbuf[cur][e_mine][j];
            float f0 = 0.f, g0 = 0.f, f1 = 0.f, g1 = 0.f;
            #pragma unroll
            for (int r = 0; r < 4; r++) {
                float4 v0 = hA[r], v1 = hB[r];
                f0 = fmaf(wfh[4*r+0], v0.x, f0); g0 = fmaf(wgh[4*r+0], v0.x, g0);
                f1 = fmaf(wfh[4*r+0], v1.x, f1); g1 = fmaf(wgh[4*r+0], v1.x, g1);
                f0 = fmaf(wfh[4*r+1], v0.y, f0); g0 = fmaf(wgh[4*r+1], v0.y, g0);
                f1 = fmaf(wfh[4*r+1], v1.y, f1); g1 = fmaf(wgh[4*r+1], v1.y, g1);
                f0 = fmaf(wfh[4*r+2], v0.z, f0); g0 = fmaf(wgh[4*r+2], v0.z, g0);
                f1 = fmaf(wfh[4*r+2], v1.z, f1); g1 = fmaf(wgh[4*r+2], v1.z, g1);
                f0 = fmaf(wfh[4*r+3], v0.w, f0); g0 = fmaf(wgh[4*r+3], v0.w, g0);
                f1 = fmaf(wfh[4*r+3], v1.w, f1); g1 = fmaf(wgh[4*r+3], v1.w, g1);
            }
            #pragma unroll
            for (int r = 0; r < 4; r++) {
                float4 v0 = uA[r], v1 = uB[r];
                f0 = fmaf(wfu[4*r+0], v0.x, f0); g0 = fmaf(wgu[4*r+0], v0.x, g0);
                f1 = fmaf(wfu[4*r+0], v1.x, f1); g1 = fmaf(wgu[4*r+0], v1.x, g1);
                f0 = fmaf(wfu[4*r+1], v0.y, f0); g0 = fmaf(wgu[4*r+1], v0.y, g0);
                f1 = fmaf(wfu[4*r+1], v1.y, f1); g1 = fmaf(wgu[4*r+1], v1.y, g1);
                f0 = fmaf(wfu[4*r+2], v0.z, f0); g0 = fmaf(wgu[4*r+2], v0.z, g0);
                f1 = fmaf(wfu[4*r+2], v1.z, f1); g1 = fmaf(wgu[4*r+2], v1.z, g1);
                f0 = fmaf(wfu[4*r+3], v0.w, f0); g0 = fmaf(wgu[4*r+3], v0.w, g0);
                f1 = fmaf(wfu[4*r+3], v1.w, f1); g1 = fmaf(wgu[4*r+3], v1.w, g1);
            }
            // 2-stage intra-group reduction
            f0 += __shfl_xor_sync(~0u, f0, 1); g0 += __shfl_xor_sync(~0u, g0, 1);
            f1 += __shfl_xor_sync(~0u, f1, 1); g1 += __shfl_xor_sync(~0u, g1, 1);
            f0 += __shfl_xor_sync(~0u, f0, 2); g0 += __shfl_xor_sync(~0u, g0, 2);
            f1 += __shfl_xor_sync(~0u, f1, 2); g1 += __shfl_xor_sync(~0u, g1, 2);

            // lane job: (elem = s&1, func = s>>1). Branchless MUFU.
            float sum = e_mine ? (is_g ? g1 : f1) : (is_g ? g0 : f0);
            float arg = sum + bias2;
            float r = sigf(is_g ? 2.f * arg : arg);
            if (is_g) r = fmaf(2.f, r, -1.f);
            // exchange f<->g across xor-2 partner (same elem)
            float other = __shfl_xor_sync(~0u, r, 2);
            float fv = is_g ? other : r;
            float gv = is_g ? r : other;
            float hn = fmaf(fv, hold - gv, gv);   // f*h + (1-f)*g
            if (s == 0) hbuf[nxt][0][j] = hn;
            if (s == 1) hbuf[nxt][1][j] = hn;
        }
        __syncthreads();   // #2: hbuf[nxt] published
    }

    // ---- epilogue: y for t = TB-1 from hbuf[TB & 1] ----
    if (wid == 8) {
        const int cur = TB & 1;
        float ha0 = hbuf[cur][0][lane], hb0 = hbuf[cur][0][lane + 32];
        float ha1 = hbuf[cur][1][lane], hb1 = hbuf[cur][1][lane + 32];
        float y00 = ha0 * wo0a + hb0 * wo0b;
        float y01 = ha0 * wo1a + hb0 * wo1b;
        float y10 = ha1 * wo0a + hb1 * wo0b;
        float y11 = ha1 * wo1a + hb1 * wo1b;
        #pragma unroll
        for (int off = 16; off; off >>= 1) {
            y00 += __shfl_xor_sync(~0u, y00, off);
            y01 += __shfl_xor_sync(~0u, y01, off);
            y10 += __shfl_xor_sync(~0u, y10, off);
            y11 += __shfl_xor_sync(~0u, y11, off);
        }
        if (lane == 0) {
            ((float2*)out)[(size_t)b0 * TB + (TB - 1)] =
                make_float2(y00 + bo0, y01 + bo1);
            ((float2*)out)[(size_t)(b0 + 1) * TB + (TB - 1)] =
                make_float2(y10 + bo0, y11 + bo1);
        }
    }
}

extern "C" void kernel_launch(void* const* d_in, const int* in_sizes, int n_in,
                              void* d_out, int out_size)
{
    const float* x   = (const float*)d_in[0];
    const float* h0  = (const float*)d_in[1];
    const float* Wa  = (const float*)d_in[2];
    const float* ba  = (const float*)d_in[3];
    const float* Wp1 = (const float*)d_in[4];
    const float* bp1 = (const float*)d_in[5];
    const float* Wp2 = (const float*)d_in[6];
    const float* bp2 = (const float*)d_in[7];
    const float* Wf  = (const float*)d_in[8];
    const float* bf  = (const float*)d_in[9];
    const float* Wg  = (const float*)d_in[10];
    const float* bg  = (const float*)d_in[11];
    const float* Wo  = (const float*)d_in[12];
    const float* bo  = (const float*)d_in[13];
    float* out = (float*)d_out;

    pgjanet_kernel<<<128, 288>>>(x, h0, Wa, ba, Wp1, bp1, Wp2, bp2,
                                 Wf, bf, Wg, bg, Wo, bo, out);
}

// round 10
// speedup vs baseline: 1.6863x; 1.6863x over previous
#include <cuda_runtime.h>

// PGJANET recurrent scan: B=256, T=2048, H=64, O=2.
// 128 blocks x 256 threads = TWO DECOUPLED ENGINES of 128 threads (4 warps),
// one batch element each, synchronized by per-engine NAMED barriers
// (bar.sync 1/2, 128) so one engine's dot work overlaps the other engine's
// latency-bound finalize. Engine thread (j = et&63, s = et>>6): unit j,
// 32-k slice s. ph1 weights (a/p1/p2/f_h/g_h, 160 floats) in registers;
// ph2 f/g u-half weights streamed from a transposed smem table [k][j]
// (conflict-free LDS.64). 2-wide partial reductions via float2 smem.
// Scalar FFMA only. x via __ldg broadcast, prefetched one segment early.

#define TB 2048

__device__ __forceinline__ float sigf(float v) {
    return __fdividef(1.f, 1.f + __expf(-v));
}
__device__ __forceinline__ float tanhfast(float v) {
    return fmaf(2.f, sigf(2.f * v), -1.f);
}
__device__ __forceinline__ void barx(int id) {
    asm volatile("bar.sync %0, 128;" :: "r"(id) : "memory");
}

__global__ void __launch_bounds__(256, 1)
pgjanet_kernel(const float* __restrict__ x,
               const float* __restrict__ h0,
               const float* __restrict__ Wa,  const float* __restrict__ ba,
               const float* __restrict__ Wp1, const float* __restrict__ bp1,
               const float* __restrict__ Wp2, const float* __restrict__ bp2,
               const float* __restrict__ Wf,  const float* __restrict__ bf,
               const float* __restrict__ Wg,  const float* __restrict__ bg,
               const float* __restrict__ Wo,  const float* __restrict__ bo,
               float* __restrict__ out)
{
    __shared__ __align__(16) float2 wtbl[64 * 64];      // 32 KB: (Wf_u,Wg_u)[k][j]
    __shared__ __align__(16) float hbuf[2][64];
    __shared__ __align__(16) float ubuf[2][64];
    __shared__ __align__(8)  float part1[2][5][64][2];  // ph1 partials [e][gate][j][s]
    __shared__ __align__(8)  float part2[2][2][64][2];  // ph2 partials [e][gate][j][s]

    const int tid  = threadIdx.x;
    const int lane = tid & 31;
    const int e    = tid >> 7;       // engine / batch element
    const int et   = tid & 127;      // thread id within engine
    const int j    = et & 63;        // hidden unit
    const int s    = et >> 6;        // k-slice 0..1 (32 wide)
    const int bid  = e + 1;          // named barrier id for this engine
    const int b0   = blockIdx.x * 2;

    // ---- ph1 weights in registers: 5 gates x 32-k slice = 160 floats ----
    float wa[32], wp1[32], wp2[32], wfh[32], wgh[32];
    {
        const float* A = Wa  + j * 65  + s * 32;
        const float* P = Wp1 + j * 65  + s * 32;
        const float* Q = Wp2 + j * 65  + s * 32;
        const float* F = Wf  + j * 128 + s * 32;
        const float* G = Wg  + j * 128 + s * 32;
        #pragma unroll
        for (int i = 0; i < 32; i++) {
            wa[i] = A[i]; wp1[i] = P[i]; wp2[i] = Q[i];
            wfh[i] = F[i]; wgh[i] = G[i];
        }
    }

    // ---- role constants ----
    float walast = 0.f, w1last = 0.f, w2last = 0.f, ba_r = 0.f, b1_r = 0.f, b2_r = 0.f;
    if (et < 64) {                                 // u-finalize owners (one per j)
        walast = Wa [j * 65 + 64]; ba_r = ba [j];
        w1last = Wp1[j * 65 + 64]; b1_r = bp1[j];
        w2last = Wp2[j * 65 + 64]; b2_r = bp2[j];
    }
    float bf_r = 0.f, bg_r = 0.f;
    if (et >= 64) { bf_r = bf[j]; bg_r = bg[j]; }  // h-finalize owners (one per j)
    float woA0 = 0.f, woB0 = 0.f, woA1 = 0.f, woB1 = 0.f, bo0 = 0.f, bo1 = 0.f;
    if (et >= 96) {                                // y warp (engine warp 3)
        woA0 = Wo[lane];      woB0 = Wo[lane + 32];
        woA1 = Wo[64 + lane]; woB1 = Wo[96 + lane];
        bo0 = bo[0]; bo1 = bo[1];
    }

    // ---- build u-half weight table (transposed, f/g interleaved) + h0 ----
    for (int idx = tid; idx < 64 * 64; idx += 256) {
        int k = idx >> 6, jj = idx & 63;
        wtbl[idx] = make_float2(Wf[jj * 128 + 64 + k], Wg[jj * 128 + 64 + k]);
    }
    if (tid < 128)
        hbuf[tid >> 6][tid & 63] = h0[(size_t)(b0 + (tid >> 6)) * 64 + (tid & 63)];
    __syncthreads();

    const float2* xg = (const float2*)x + (size_t)(b0 + e) * TB;
    float2* outp = (float2*)out + (size_t)(b0 + e) * TB;

    #pragma unroll 1
    for (int t = 0; t < TB; t++) {
        // prefetch x[t] early (used ~400 cyc later in u-finalize)
        float2 xv = make_float2(0.f, 0.f);
        if (et < 64) xv = __ldg(xg + t);

        // ==== ph1: a/p1/p2/f_h/g_h partial dots over h slice s ====
        {
            const float4* hp = (const float4*)(hbuf[e] + s * 32);
            float aa = 0.f, ap = 0.f, aq = 0.f, af = 0.f, ag = 0.f;
            #pragma unroll
            for (int r = 0; r < 8; r++) {
                float4 v = hp[r];
                aa = fmaf(wa [4*r+0], v.x, aa); ap = fmaf(wp1[4*r+0], v.x, ap);
                aq = fmaf(wp2[4*r+0], v.x, aq); af = fmaf(wfh[4*r+0], v.x, af);
                ag = fmaf(wgh[4*r+0], v.x, ag);
                aa = fmaf(wa [4*r+1], v.y, aa); ap = fmaf(wp1[4*r+1], v.y, ap);
                aq = fmaf(wp2[4*r+1], v.y, aq); af = fmaf(wfh[4*r+1], v.y, af);
                ag = fmaf(wgh[4*r+1], v.y, ag);
                aa = fmaf(wa [4*r+2], v.z, aa); ap = fmaf(wp1[4*r+2], v.z, ap);
                aq = fmaf(wp2[4*r+2], v.z, aq); af = fmaf(wfh[4*r+2], v.z, af);
                ag = fmaf(wgh[4*r+2], v.z, ag);
                aa = fmaf(wa [4*r+3], v.w, aa); ap = fmaf(wp1[4*r+3], v.w, ap);
                aq = fmaf(wp2[4*r+3], v.w, aq); af = fmaf(wfh[4*r+3], v.w, af);
                ag = fmaf(wgh[4*r+3], v.w, ag);
            }
            part1[e][0][j][s] = aa;
            part1[e][1][j][s] = ap;
            part1[e][2][j][s] = aq;
            part1[e][3][j][s] = af;
            part1[e][4][j][s] = ag;
        }
        barx(bid);   // #1: ph1 partials ready

        if (et < 64) {
            // ==== u-finalize (engine warps 0-1) ====
            float2 pa = *(const float2*)part1[e][0][j];
            float2 pp = *(const float2*)part1[e][1][j];
            float2 pq = *(const float2*)part1[e][2][j];
            float s2 = fmaf(xv.x, xv.x, xv.y * xv.y);
            float ri = rsqrtf(s2);
            float amp, ct, st;
            if (s2 > 0.f) { amp = s2 * ri; ct = xv.x * ri; st = xv.y * ri; }
            else          { amp = 0.f;     ct = 1.f;       st = 0.f; }
            float av  = tanhfast(fmaf(amp, walast, pa.x + pa.y + ba_r));
            float p1v = tanhfast(fmaf(ct,  w1last, pp.x + pp.y + b1_r));
            float p2v = tanhfast(fmaf(st,  w2last, pq.x + pq.y + b2_r));
            ubuf[e][j] = (av - av * av) * (p1v - p1v * p1v) * (p2v - p2v * p2v);
        } else if (et >= 96 && t > 0) {
            // ==== y output for step t-1 (engine warp 3; hbuf still holds h_{t-1}) ====
            float ha = hbuf[e][lane], hb = hbuf[e][lane + 32];
            float y0 = ha * woA0 + hb * woB0;
            float y1 = ha * woA1 + hb * woB1;
            #pragma unroll
            for (int off = 16; off; off >>= 1) {
                y0 += __shfl_xor_sync(~0u, y0, off);
                y1 += __shfl_xor_sync(~0u, y1, off);
            }
            if (lane == 0) outp[t - 1] = make_float2(y0 + bo0, y1 + bo1);
        }
        barx(bid);   // #2: ubuf ready

        // ==== ph2: f/g u-half partial dots, weights streamed from smem table ====
        {
            const float4* up = (const float4*)(ubuf[e] + s * 32);
            const float2* tb = wtbl + (s * 32) * 64 + j;
            float cf = 0.f, cg = 0.f;
            #pragma unroll
            for (int r = 0; r < 8; r++) {
                float4 v = up[r];
                float2 w0 = tb[(4*r+0) * 64];
                cf = fmaf(w0.x, v.x, cf); cg = fmaf(w0.y, v.x, cg);
                float2 w1 = tb[(4*r+1) * 64];
                cf = fmaf(w1.x, v.y, cf); cg = fmaf(w1.y, v.y, cg);
                float2 w2 = tb[(4*r+2) * 64];
                cf = fmaf(w2.x, v.z, cf); cg = fmaf(w2.y, v.z, cg);
                float2 w3 = tb[(4*r+3) * 64];
                cf = fmaf(w3.x, v.w, cf); cg = fmaf(w3.y, v.w, cg);
            }
            part2[e][0][j][s] = cf;
            part2[e][1][j][s] = cg;
        }
        barx(bid);   // #3: ph2 partials ready

        if (et >= 64) {
            // ==== h-finalize (engine warps 2-3) ====
            float hold = hbuf[e][j];
            float2 f1 = *(const float2*)part1[e][3][j];
            float2 g1 = *(const float2*)part1[e][4][j];
            float2 f2 = *(const float2*)part2[e][0][j];
            float2 g2 = *(const float2*)part2[e][1][j];
            float f = sigf(f1.x + f1.y + f2.x + f2.y + bf_r);
            float g = tanhfast(g1.x + g1.y + g2.x + g2.y + bg_r);
            hbuf[e][j] = fmaf(f, hold - g, g);   // f*h + (1-f)*g
        }
        barx(bid);   // #4: h_t published
    }

    // ---- epilogue: y for t = TB-1 ----
    if (et >= 96) {
        float ha = hbuf[e][lane], hb = hbuf[e][lane + 32];
        float y0 = ha * woA0 + hb * woB0;
        float y1 = ha * woA1 + hb * woB1;
        #pragma unroll
        for (int off = 16; off; off >>= 1) {
            y0 += __shfl_xor_sync(~0u, y0, off);
            y1 += __shfl_xor_sync(~0u, y1, off);
        }
        if (lane == 0) outp[TB - 1] = make_float2(y0 + bo0, y1 + bo1);
    }
}

extern "C" void kernel_launch(void* const* d_in, const int* in_sizes, int n_in,
                              void* d_out, int out_size)
{
    const float* x   = (const float*)d_in[0];
    const float* h0  = (const float*)d_in[1];
    const float* Wa  = (const float*)d_in[2];
    const float* ba  = (const float*)d_in[3];
    const float* Wp1 = (const float*)d_in[4];
    const float* bp1 = (const float*)d_in[5];
    const float* Wp2 = (const float*)d_in[6];
    const float* bp2 = (const float*)d_in[7];
    const float* Wf  = (const float*)d_in[8];
    const float* bf  = (const float*)d_in[9];
    const float* Wg  = (const float*)d_in[10];
    const float* bg  = (const float*)d_in[11];
    const float* Wo  = (const float*)d_in[12];
    const float* bo  = (const float*)d_in[13];
    float* out = (float*)d_out;

    pgjanet_kernel<<<128, 256>>>(x, h0, Wa, ba, Wp1, bp1, Wp2, bp2,
                                 Wf, bf, Wg, bg, Wo, bo, out);
}

// round 11
// speedup vs baseline: 1.8384x; 1.0902x over previous
#include <cuda_runtime.h>

// PGJANET recurrent scan: B=256, T=2048, H=64, O=2.
// R4 base (validated fastest structure: 128 blocks x 256 threads, 2 elems per
// block, 4 barriers/step, smem partial reduction, scalar FFMA, weights in
// registers) + three latency cuts:
//  1) tanh.approx.f32 (MUFU) for a/p1/p2 (u-path is damped; f/g stay exact)
//  2) x-scalar processing (rsqrt chain) hoisted into the ph1 fma segment
//  3) partial stores packed float2 across elems (STS.64)

#define TB 2048

__device__ __forceinline__ float sigf(float v) {
    return __fdividef(1.f, 1.f + __expf(-v));
}
__device__ __forceinline__ float tanhfast(float v) {          // exact-ish path
    return fmaf(2.f, sigf(2.f * v), -1.f);
}
__device__ __forceinline__ float tanhmufu(float v) {          // single MUFU
    float r; asm("tanh.approx.f32 %0, %1;" : "=f"(r) : "f"(v)); return r;
}

__global__ void __launch_bounds__(256, 1)
pgjanet_kernel(const float* __restrict__ x,
               const float* __restrict__ h0,
               const float* __restrict__ Wa,  const float* __restrict__ ba,
               const float* __restrict__ Wp1, const float* __restrict__ bp1,
               const float* __restrict__ Wp2, const float* __restrict__ bp2,
               const float* __restrict__ Wf,  const float* __restrict__ bf,
               const float* __restrict__ Wg,  const float* __restrict__ bg,
               const float* __restrict__ Wo,  const float* __restrict__ bo,
               float* __restrict__ out)
{
    __shared__ __align__(16) float2 xb[2][TB];        // 32 KB
    __shared__ __align__(16) float hbuf[2][64];
    __shared__ __align__(16) float ubuf[2][64];
    __shared__ __align__(8)  float2 part[5][4][64];   // packed (e0,e1), 10 KB

    const int tid  = threadIdx.x;
    const int lane = tid & 31;
    const int wid  = tid >> 5;
    const int j    = tid & 63;      // hidden unit
    const int s    = tid >> 6;      // k-slice 0..3
    const int b0   = blockIdx.x * 2;

    // ---- weights in registers (112 floats) ----
    float wa[16], wp1[16], wp2[16], wfh[16], wgh[16], wfu[16], wgu[16];
    {
        const float* A = Wa  + j * 65 + s * 16;
        const float* P = Wp1 + j * 65 + s * 16;
        const float* Q = Wp2 + j * 65 + s * 16;
        const float* F = Wf  + j * 128 + s * 16;
        const float* G = Wg  + j * 128 + s * 16;
        #pragma unroll
        for (int i = 0; i < 16; i++) {
            wa[i]  = A[i];  wp1[i] = P[i];  wp2[i] = Q[i];
            wfh[i] = F[i];  wgh[i] = G[i];
            wfu[i] = F[64 + i]; wgu[i] = G[64 + i];
        }
    }

    // ---- finalize constants ----
    float walast = 0.f, w1last = 0.f, w2last = 0.f, ba_r = 0.f, b1_r = 0.f, b2_r = 0.f;
    if (tid < 128) {                        // u-finalize: (e = tid>>6, j)
        walast = Wa [j * 65 + 64]; ba_r = ba [j];
        w1last = Wp1[j * 65 + 64]; b1_r = bp1[j];
        w2last = Wp2[j * 65 + 64]; b2_r = bp2[j];
    }
    float bf_r = 0.f, bg_r = 0.f;
    if (tid >= 128) { bf_r = bf[j]; bg_r = bg[j]; }   // h-finalize: (e=(tid>>6)&1, j)
    float woA0 = 0.f, woB0 = 0.f, woA1 = 0.f, woB1 = 0.f, bo0 = 0.f, bo1 = 0.f;
    if (wid >= 6) {                         // y-output: warps 6,7 -> elem 0,1
        woA0 = Wo[lane];      woB0 = Wo[lane + 32];
        woA1 = Wo[64 + lane]; woB1 = Wo[96 + lane];
        bo0 = bo[0]; bo1 = bo[1];
    }

    // ---- preload x + h0 ----
    {
        const float2* xg0 = (const float2*)x + (size_t)b0 * TB;
        const float2* xg1 = (const float2*)x + (size_t)(b0 + 1) * TB;
        for (int i = tid; i < TB; i += 256) { xb[0][i] = xg0[i]; xb[1][i] = xg1[i]; }
    }
    if (tid < 128) hbuf[tid >> 6][j] = h0[(size_t)(b0 + (tid >> 6)) * 64 + j];
    __syncthreads();

    #pragma unroll 1
    for (int t = 0; t < TB; t++) {
        // hoisted x-scalars (u-finalize threads only; hides under ph1 FMA)
        float amp = 0.f, ct = 1.f, st = 0.f;
        if (tid < 128) {
            const int e = tid >> 6;
            float2 xv = xb[e][t];
            float s2 = fmaf(xv.x, xv.x, xv.y * xv.y);
            float ri = rsqrtf(s2);
            bool nz = (s2 > 0.f);
            amp = nz ? s2 * ri : 0.f;
            ct  = nz ? xv.x * ri : 1.f;
            st  = nz ? xv.y * ri : 0.f;
        }

        // ==== phase 1: partial dots (5 gates x 2 elems, slice s) ====
        {
            const float4* h0p = (const float4*)&hbuf[0][s * 16];
            const float4* h1p = (const float4*)&hbuf[1][s * 16];
            float a0 = 0.f, p0 = 0.f, q0 = 0.f, f0 = 0.f, g0 = 0.f;
            float a1 = 0.f, p1 = 0.f, q1 = 0.f, f1 = 0.f, g1 = 0.f;
            #pragma unroll
            for (int r = 0; r < 4; r++) {
                float4 v0 = h0p[r], v1 = h1p[r];
                #pragma unroll
                for (int c = 0; c < 4; c++) {
                    float w_a = wa[4*r+c], w_p = wp1[4*r+c], w_q = wp2[4*r+c];
                    float w_f = wfh[4*r+c], w_g = wgh[4*r+c];
                    float e0 = (c==0)?v0.x:(c==1)?v0.y:(c==2)?v0.z:v0.w;
                    float e1 = (c==0)?v1.x:(c==1)?v1.y:(c==2)?v1.z:v1.w;
                    a0 = fmaf(w_a, e0, a0); a1 = fmaf(w_a, e1, a1);
                    p0 = fmaf(w_p, e0, p0); p1 = fmaf(w_p, e1, p1);
                    q0 = fmaf(w_q, e0, q0); q1 = fmaf(w_q, e1, q1);
                    f0 = fmaf(w_f, e0, f0); f1 = fmaf(w_f, e1, f1);
                    g0 = fmaf(w_g, e0, g0); g1 = fmaf(w_g, e1, g1);
                }
            }
            part[0][s][j] = make_float2(a0, a1);
            part[1][s][j] = make_float2(p0, p1);
            part[2][s][j] = make_float2(q0, q1);
            part[3][s][j] = make_float2(f0, f1);
            part[4][s][j] = make_float2(g0, g1);
        }
        __syncthreads();   // #1

        if (tid < 128) {
            // ==== u-finalize (warps 0-3); tanh via MUFU (damped path) ====
            const int e = tid >> 6;
            float2 pa0 = part[0][0][j], pa1 = part[0][1][j],
                   pa2 = part[0][2][j], pa3 = part[0][3][j];
            float2 pp0 = part[1][0][j], pp1 = part[1][1][j],
                   pp2 = part[1][2][j], pp3 = part[1][3][j];
            float2 pq0 = part[2][0][j], pq1 = part[2][1][j],
                   pq2 = part[2][2][j], pq3 = part[2][3][j];
            float sa = e ? (pa0.y + pa1.y) + (pa2.y + pa3.y)
                         : (pa0.x + pa1.x) + (pa2.x + pa3.x);
            float sp = e ? (pp0.y + pp1.y) + (pp2.y + pp3.y)
                         : (pp0.x + pp1.x) + (pp2.x + pp3.x);
            float sq = e ? (pq0.y + pq1.y) + (pq2.y + pq3.y)
                         : (pq0.x + pq1.x) + (pq2.x + pq3.x);
            float av  = tanhmufu(fmaf(amp, walast, sa + ba_r));
            float p1v = tanhmufu(fmaf(ct,  w1last, sp + b1_r));
            float p2v = tanhmufu(fmaf(st,  w2last, sq + b2_r));
            ubuf[e][j] = (av - av * av) * (p1v - p1v * p1v) * (p2v - p2v * p2v);
        } else if (wid >= 6 && t > 0) {
            // ==== y output for step t-1 (warps 6-7, overlapped) ====
            const int e = wid - 6;
            float ha = hbuf[e][lane], hb = hbuf[e][lane + 32];
            float y0 = ha * woA0 + hb * woB0;
            float y1 = ha * woA1 + hb * woB1;
            #pragma unroll
            for (int off = 16; off; off >>= 1) {
                y0 += __shfl_xor_sync(~0u, y0, off);
                y1 += __shfl_xor_sync(~0u, y1, off);
            }
            if (lane == 0)
                ((float2*)out)[(size_t)(b0 + e) * TB + (t - 1)] =
                    make_float2(y0 + bo0, y1 + bo1);
        }
        __syncthreads();   // #2

        // ==== phase 2: f/g u-half partial dots (slice s, both elems) ====
        {
            const float4* u0p = (const float4*)&ubuf[0][s * 16];
            const float4* u1p = (const float4*)&ubuf[1][s * 16];
            float cf0 = 0.f, cg0 = 0.f, cf1 = 0.f, cg1 = 0.f;
            #pragma unroll
            for (int r = 0; r < 4; r++) {
                float4 v0 = u0p[r], v1 = u1p[r];
                #pragma unroll
                for (int c = 0; c < 4; c++) {
                    float w_f = wfu[4*r+c], w_g = wgu[4*r+c];
                    float e0 = (c==0)?v0.x:(c==1)?v0.y:(c==2)?v0.z:v0.w;
                    float e1 = (c==0)?v1.x:(c==1)?v1.y:(c==2)?v1.z:v1.w;
                    cf0 = fmaf(w_f, e0, cf0); cf1 = fmaf(w_f, e1, cf1);
                    cg0 = fmaf(w_g, e0, cg0); cg1 = fmaf(w_g, e1, cg1);
                }
            }
            part[0][s][j] = make_float2(cf0, cf1);
            part[1][s][j] = make_float2(cg0, cg1);
        }
        __syncthreads();   // #3

        if (tid >= 128) {
            // ==== h-finalize (warps 4-7); f/g exact ====
            const int e = (tid >> 6) & 1;
            float2 pf0 = part[0][0][j], pf1 = part[0][1][j],
                   pf2 = part[0][2][j], pf3 = part[0][3][j];
            float2 pg0 = part[1][0][j], pg1 = part[1][1][j],
                   pg2 = part[1][2][j], pg3 = part[1][3][j];
            float2 hf0 = part[3][0][j], hf1 = part[3][1][j],
                   hf2 = part[3][2][j], hf3 = part[3][3][j];
            float2 hg0 = part[4][0][j], hg1 = part[4][1][j],
                   hg2 = part[4][2][j], hg3 = part[4][3][j];
            float sf = e ? (pf0.y + pf1.y) + (pf2.y + pf3.y) + (hf0.y + hf1.y) + (hf2.y + hf3.y)
                         : (pf0.x + pf1.x) + (pf2.x + pf3.x) + (hf0.x + hf1.x) + (hf2.x + hf3.x);
            float sg = e ? (pg0.y + pg1.y) + (pg2.y + pg3.y) + (hg0.y + hg1.y) + (hg2.y + hg3.y)
                         : (pg0.x + pg1.x) + (pg2.x + pg3.x) + (hg0.x + hg1.x) + (hg2.x + hg3.x);
            float f = sigf(sf + bf_r);
            float g = tanhfast(sg + bg_r);
            float hold = hbuf[e][j];
            hbuf[e][j] = fmaf(f, hold - g, g);   // f*h + (1-f)*g
        }
        __syncthreads();   // #4
    }

    // ---- epilogue: y for t = TB-1 ----
    if (wid >= 6) {
        const int e = wid - 6;
        float ha = hbuf[e][lane], hb = hbuf[e][lane + 32];
        float y0 = ha * woA0 + hb * woB0;
        float y1 = ha * woA1 + hb * woB1;
        #pragma unroll
        for (int off = 16; off; off >>= 1) {
            y0 += __shfl_xor_sync(~0u, y0, off);
            y1 += __shfl_xor_sync(~0u, y1, off);
        }
        if (lane == 0)
            ((float2*)out)[(size_t)(b0 + e) * TB + (TB - 1)] =
                make_float2(y0 + bo0, y1 + bo1);
    }
}

extern "C" void kernel_launch(void* const* d_in, const int* in_sizes, int n_in,
                              void* d_out, int out_size)
{
    const float* x   = (const float*)d_in[0];
    const float* h0  = (const float*)d_in[1];
    const float* Wa  = (const float*)d_in[2];
    const float* ba  = (const float*)d_in[3];
    const float* Wp1 = (const float*)d_in[4];
    const float* bp1 = (const float*)d_in[5];
    const float* Wp2 = (const float*)d_in[6];
    const float* bp2 = (const float*)d_in[7];
    const float* Wf  = (const float*)d_in[8];
    const float* bf  = (const float*)d_in[9];
    const float* Wg  = (const float*)d_in[10];
    const float* bg  = (const float*)d_in[11];
    const float* Wo  = (const float*)d_in[12];
    const float* bo  = (const float*)d_in[13];
    float* out = (float*)d_out;

    pgjanet_kernel<<<128, 256>>>(x, h0, Wa, ba, Wp1, bp1, Wp2, bp2,
                                 Wf, bf, Wg, bg, Wo, bo, out);
}